// round 4
// baseline (speedup 1.0000x reference)
#include <cuda_runtime.h>
#include <cuda_bf16.h>

#define NVX 50000
#define NEX 10000
#define HD  256
#define PX  400000

// ---------------- scratch (static device globals; no runtime alloc) ----------------
__device__ float g_ve[(size_t)NVX * HD];   // relu(v @ W1^T + b1) * n_weight
__device__ float g_ev[(size_t)NEX * HD];   // relu(e_out @ W2^T + b2) * e_weight
__device__ int g_cnt_e[NEX];
__device__ int g_off_e[NEX + 1];
__device__ int g_cur_e[NEX];
__device__ int g_perm_e[PX];
__device__ int g_cnt_v[NVX];
__device__ int g_off_v[NVX + 1];
__device__ int g_cur_v[NVX];
__device__ int g_perm_v[PX];

// ---------------- CSR build (fused edge+vertex) ----------------
__global__ void k_zero_all() {
    int i = blockIdx.x * blockDim.x + threadIdx.x;
    if (i < NEX) g_cnt_e[i] = 0;
    if (i < NVX) g_cnt_v[i] = 0;
}

__global__ void k_hist_all(const int* __restrict__ eidx, const int* __restrict__ vidx) {
    int i = blockIdx.x * blockDim.x + threadIdx.x;
    if (i < PX) {
        atomicAdd(&g_cnt_e[eidx[i]], 1);
        atomicAdd(&g_cnt_v[vidx[i]], 1);
    }
}

// grid=2: block 0 scans edge counters, block 1 vertex counters.
__global__ void k_scan_all() {
    const bool EDGE = (blockIdx.x == 0);
    const int n = EDGE ? NEX : NVX;
    const int items = (n + 1023) / 1024;
    const int* cnt = EDGE ? g_cnt_e : g_cnt_v;
    int* off = EDGE ? g_off_e : g_off_v;
    int* cur = EDGE ? g_cur_e : g_cur_v;

    __shared__ int wsum[32];
    int t = threadIdx.x;            // blockDim.x == 1024
    int lane = t & 31, wid = t >> 5;
    int start = t * items;
    int end = min(start + items, n);

    int sum = 0;
    for (int i = start; i < end; i++) sum += cnt[i];

    int v = sum;
#pragma unroll
    for (int s = 1; s < 32; s <<= 1) {
        int y = __shfl_up_sync(0xffffffffu, v, s);
        if (lane >= s) v += y;
    }
    if (lane == 31) wsum[wid] = v;
    __syncthreads();
    if (wid == 0) {
        int w = wsum[lane];
        int vi = w;
#pragma unroll
        for (int s = 1; s < 32; s <<= 1) {
            int y = __shfl_up_sync(0xffffffffu, vi, s);
            if (lane >= s) vi += y;
        }
        wsum[lane] = vi - w;
    }
    __syncthreads();

    int excl = wsum[wid] + (v - sum);
    int run = excl;
    for (int i = start; i < end; i++) {
        off[i] = run;
        cur[i] = run;
        run += cnt[i];
    }
    if (t == 1023) off[n] = run;
}

__global__ void k_fill_all(const int* __restrict__ eidx, const int* __restrict__ vidx) {
    int i = blockIdx.x * blockDim.x + threadIdx.x;
    if (i < PX) {
        int pe = atomicAdd(&g_cur_e[eidx[i]], 1);
        g_perm_e[pe] = i;
        int pv = atomicAdd(&g_cur_v[vidx[i]], 1);
        g_perm_v[pv] = i;
    }
}

// ---------------- split-bf16 tensor-core GEMM with register-prefetch pipeline ----
// C[m,n] = relu(sum_k A[m,k]*B[n,k] + bias[n]) * rowscale[m]
// x = hi + lo (bf16 each); C = Ah*Bh + Ah*Bl + Al*Bh via mma.m16n8k16.bf16 (fp32 acc).
#define BM 128
#define BN 128
#define BK 32
#define SP 20   // smem row stride in b32 units (16 data + 4 pad -> conflict-free)

__device__ __forceinline__ unsigned pack_bf16(float x0, float x1) {
    __nv_bfloat16 h0 = __float2bfloat16(x0);
    __nv_bfloat16 h1 = __float2bfloat16(x1);
    return (unsigned)__bfloat16_as_ushort(h0) | ((unsigned)__bfloat16_as_ushort(h1) << 16);
}

__device__ __forceinline__ void mma_bf16(float* c, const unsigned* a, const unsigned* b) {
    asm volatile(
        "mma.sync.aligned.m16n8k16.row.col.f32.bf16.bf16.f32 "
        "{%0,%1,%2,%3}, {%4,%5,%6,%7}, {%8,%9}, {%0,%1,%2,%3};"
        : "+f"(c[0]), "+f"(c[1]), "+f"(c[2]), "+f"(c[3])
        : "r"(a[0]), "r"(a[1]), "r"(a[2]), "r"(a[3]), "r"(b[0]), "r"(b[1]));
}

template <bool VE>
__global__ void __launch_bounds__(256)
k_gemm_bf16(const float* __restrict__ A, const float* __restrict__ B,
            const float* __restrict__ bias, const float* __restrict__ rowscale, int M) {
    float* C = VE ? g_ve : g_ev;
    __shared__ unsigned As_hi[BM * SP], As_lo[BM * SP];
    __shared__ unsigned Bs_hi[BN * SP], Bs_lo[BN * SP];

    const int tid = threadIdx.x;
    const int bm = blockIdx.x * BM;
    const int bn = blockIdx.y * BN;
    const int wid = tid >> 5, lane = tid & 31;
    const int gid = lane >> 2, tid4 = lane & 3;
    const int wm = (wid & 1) * 64;
    const int wn = (wid >> 1) * 32;

    // per-thread staging slots: 4 float4 for A, 4 for B per k-tile
    const int srow = tid >> 3;       // 0..31 base row (i adds +32)
    const int sc4 = tid & 7;         // float4 column within BK

    float acc[4][4][4];
#pragma unroll
    for (int mt = 0; mt < 4; mt++)
#pragma unroll
        for (int nt = 0; nt < 4; nt++)
#pragma unroll
            for (int q = 0; q < 4; q++) acc[mt][nt][q] = 0.f;

    float4 pA[4], pB[4];

    // ---- pipeline helpers (macros keep registers local) ----
#define LDG_TILE(K0)                                                          \
    {                                                                         \
        _Pragma("unroll")                                                     \
        for (int i = 0; i < 4; i++) {                                         \
            int row = srow + i * 32;                                          \
            int gm = bm + row;                                                \
            pA[i] = (gm < M) ? *(const float4*)&A[(size_t)gm * HD + (K0) + sc4 * 4] \
                             : make_float4(0.f, 0.f, 0.f, 0.f);               \
            pB[i] = *(const float4*)&B[(size_t)(bn + row) * HD + (K0) + sc4 * 4];   \
        }                                                                     \
    }

#define STS_TILE()                                                            \
    {                                                                         \
        _Pragma("unroll")                                                     \
        for (int i = 0; i < 4; i++) {                                         \
            int row = srow + i * 32;                                          \
            float4 av = pA[i];                                                \
            float h0 = __bfloat162float(__float2bfloat16(av.x));              \
            float h1 = __bfloat162float(__float2bfloat16(av.y));              \
            float h2 = __bfloat162float(__float2bfloat16(av.z));              \
            float h3 = __bfloat162float(__float2bfloat16(av.w));              \
            As_hi[row * SP + sc4 * 2 + 0] = pack_bf16(h0, h1);                \
            As_hi[row * SP + sc4 * 2 + 1] = pack_bf16(h2, h3);                \
            As_lo[row * SP + sc4 * 2 + 0] = pack_bf16(av.x - h0, av.y - h1);  \
            As_lo[row * SP + sc4 * 2 + 1] = pack_bf16(av.z - h2, av.w - h3);  \
            float4 wv = pB[i];                                                \
            float w0 = __bfloat162float(__float2bfloat16(wv.x));              \
            float w1 = __bfloat162float(__float2bfloat16(wv.y));              \
            float w2 = __bfloat162float(__float2bfloat16(wv.z));              \
            float w3 = __bfloat162float(__float2bfloat16(wv.w));              \
            Bs_hi[row * SP + sc4 * 2 + 0] = pack_bf16(w0, w1);                \
            Bs_hi[row * SP + sc4 * 2 + 1] = pack_bf16(w2, w3);                \
            Bs_lo[row * SP + sc4 * 2 + 0] = pack_bf16(wv.x - w0, wv.y - w1);  \
            Bs_lo[row * SP + sc4 * 2 + 1] = pack_bf16(wv.z - w2, wv.w - w3);  \
        }                                                                     \
    }

#define COMPUTE_TILE()                                                        \
    {                                                                         \
        _Pragma("unroll")                                                     \
        for (int ks = 0; ks < 2; ks++) {                                      \
            unsigned ah[4][4], al[4][4], bh[4][2], bl[4][2];                  \
            _Pragma("unroll")                                                 \
            for (int mt = 0; mt < 4; mt++) {                                  \
                int r = wm + mt * 16 + gid;                                   \
                int c = ks * 8 + tid4;                                        \
                ah[mt][0] = As_hi[r * SP + c];                                \
                ah[mt][1] = As_hi[(r + 8) * SP + c];                          \
                ah[mt][2] = As_hi[r * SP + c + 4];                            \
                ah[mt][3] = As_hi[(r + 8) * SP + c + 4];                      \
                al[mt][0] = As_lo[r * SP + c];                                \
                al[mt][1] = As_lo[(r + 8) * SP + c];                          \
                al[mt][2] = As_lo[r * SP + c + 4];                            \
                al[mt][3] = As_lo[(r + 8) * SP + c + 4];                      \
            }                                                                 \
            _Pragma("unroll")                                                 \
            for (int nt = 0; nt < 4; nt++) {                                  \
                int r = wn + nt * 8 + gid;                                    \
                int c = ks * 8 + tid4;                                        \
                bh[nt][0] = Bs_hi[r * SP + c];                                \
                bh[nt][1] = Bs_hi[r * SP + c + 4];                            \
                bl[nt][0] = Bs_lo[r * SP + c];                                \
                bl[nt][1] = Bs_lo[r * SP + c + 4];                            \
            }                                                                 \
            _Pragma("unroll")                                                 \
            for (int mt = 0; mt < 4; mt++)                                    \
                _Pragma("unroll")                                             \
                for (int nt = 0; nt < 4; nt++) {                              \
                    mma_bf16(acc[mt][nt], ah[mt], bh[nt]);                    \
                    mma_bf16(acc[mt][nt], ah[mt], bl[nt]);                    \
                    mma_bf16(acc[mt][nt], al[mt], bh[nt]);                    \
                }                                                             \
        }                                                                     \
    }

    // ---- pipelined main loop over 8 k-tiles ----
    LDG_TILE(0);
    STS_TILE();
    __syncthreads();
#pragma unroll
    for (int k0 = 1; k0 < HD / BK; k0++) {
        LDG_TILE(k0 * BK);     // prefetch next tile while computing current
        COMPUTE_TILE();
        __syncthreads();       // everyone done reading smem
        STS_TILE();
        __syncthreads();       // writes visible
    }
    COMPUTE_TILE();

#undef LDG_TILE
#undef STS_TILE
#undef COMPUTE_TILE

    // ---- epilogue: bias + relu + rowscale ----
#pragma unroll
    for (int mt = 0; mt < 4; mt++) {
        int rm0 = bm + wm + mt * 16 + gid;
        int rm1 = rm0 + 8;
        float sc0 = (rm0 < M) ? rowscale[rm0] : 0.f;
        float sc1 = (rm1 < M) ? rowscale[rm1] : 0.f;
#pragma unroll
        for (int nt = 0; nt < 4; nt++) {
            int cn = bn + wn + nt * 8 + tid4 * 2;
            float b0f = bias[cn], b1f = bias[cn + 1];
            if (rm0 < M) {
                float2 o;
                o.x = fmaxf(acc[mt][nt][0] + b0f, 0.f) * sc0;
                o.y = fmaxf(acc[mt][nt][1] + b1f, 0.f) * sc0;
                *(float2*)&C[(size_t)rm0 * HD + cn] = o;
            }
            if (rm1 < M) {
                float2 o;
                o.x = fmaxf(acc[mt][nt][2] + b0f, 0.f) * sc1;
                o.y = fmaxf(acc[mt][nt][3] + b1f, 0.f) * sc1;
                *(float2*)&C[(size_t)rm1 * HD + cn] = o;
            }
        }
    }
}

// ---------------- pull-based accumulation ----------------
__global__ void k_edge_accum(const float* __restrict__ e, const int* __restrict__ pairs_v,
                             const float* __restrict__ nrw, const float* __restrict__ ers,
                             float* __restrict__ e_out) {
    __shared__ int srow[256];
    __shared__ float sw[256];
    int j = blockIdx.x;
    int h = threadIdx.x;
    int s = g_off_e[j], t = g_off_e[j + 1];
    float acc = e[(size_t)j * HD + h];
    for (int c = s; c < t; c += 256) {
        int i = c + h;
        if (i < t) {
            int p = g_perm_e[i];
            srow[h] = pairs_v[p];
            sw[h] = nrw[p];
        }
        __syncthreads();
        int m = min(256, t - c);
#pragma unroll 4
        for (int q = 0; q < m; q++)
            acc = fmaf(g_ve[(size_t)srow[q] * HD + h], sw[q], acc);
        __syncthreads();
    }
    e_out[(size_t)j * HD + h] = acc / ers[j];
}

__global__ void k_vertex_accum(const float* __restrict__ v, const int* __restrict__ pairs_e,
                               const float* __restrict__ erw, const float* __restrict__ nrs,
                               const float* __restrict__ nw, float* __restrict__ v_out) {
    __shared__ int srow[256];
    __shared__ float sw[256];
    int i0 = blockIdx.x;
    int h = threadIdx.x;
    int s = g_off_v[i0], t = g_off_v[i0 + 1];
    float acc = v[(size_t)i0 * HD + h] * nw[i0];
    for (int c = s; c < t; c += 256) {
        int i = c + h;
        if (i < t) {
            int p = g_perm_v[i];
            srow[h] = pairs_e[p];
            sw[h] = erw[p];
        }
        __syncthreads();
        int m = min(256, t - c);
#pragma unroll 4
        for (int q = 0; q < m; q++)
            acc = fmaf(g_ev[(size_t)srow[q] * HD + h], sw[q], acc);
        __syncthreads();
    }
    v_out[(size_t)i0 * HD + h] = acc / nrs[i0];
}

// ---------------- launcher: fork/join capture-legal two-stream graph ----------------
static cudaStream_t g_s1 = nullptr;
static cudaEvent_t g_evFork = nullptr, g_evCsr = nullptr;

extern "C" void kernel_launch(void* const* d_in, const int* in_sizes, int n_in,
                              void* d_out, int out_size) {
    const float* v            = (const float*)d_in[0];
    const float* e            = (const float*)d_in[1];
    const float* W1           = (const float*)d_in[2];
    const float* b1           = (const float*)d_in[3];
    const float* W2           = (const float*)d_in[4];
    const float* b2           = (const float*)d_in[5];
    const float* n_weight     = (const float*)d_in[6];
    const float* e_weight     = (const float*)d_in[7];
    const float* n_reg_weight = (const float*)d_in[8];
    const float* e_reg_weight = (const float*)d_in[9];
    const float* e_reg_sum    = (const float*)d_in[10];
    const float* n_reg_sum    = (const float*)d_in[11];
    const int*   pairs_v      = (const int*)d_in[12];
    const int*   eidx         = (const int*)d_in[13];
    const int*   pairs_e      = (const int*)d_in[14];
    const int*   vidx         = (const int*)d_in[15];

    float* v_out = (float*)d_out;                              // [NVX, HD]
    float* e_out = (float*)d_out + (size_t)NVX * HD;           // [NEX, HD]

    if (!g_s1) {   // first (uncaptured, correctness) call creates infra; capture call reuses
        cudaStreamCreateWithFlags(&g_s1, cudaStreamNonBlocking);
        cudaEventCreateWithFlags(&g_evFork, cudaEventDisableTiming);
        cudaEventCreateWithFlags(&g_evCsr, cudaEventDisableTiming);
    }

    // fork: CSR build chain runs on g_s1 concurrently with GEMM1 on the main stream
    cudaEventRecord(g_evFork, 0);
    cudaStreamWaitEvent(g_s1, g_evFork, 0);

    k_zero_all<<<(NVX + 255) / 256, 256, 0, g_s1>>>();
    k_hist_all<<<(PX + 255) / 256, 256, 0, g_s1>>>(eidx, vidx);
    k_scan_all<<<2, 1024, 0, g_s1>>>();

    // GEMM1 on main stream (4th submitted launch -> lands in the ncu sample window)
    dim3 g1((NVX + BM - 1) / BM, HD / BN);
    k_gemm_bf16<true><<<g1, 256>>>(v, W1, b1, n_weight, NVX);

    k_fill_all<<<(PX + 255) / 256, 256, 0, g_s1>>>(eidx, vidx);

    // join: edge_accum needs CSR_e + GEMM1; vertex_accum later needs CSR_v (also joined)
    cudaEventRecord(g_evCsr, g_s1);
    cudaStreamWaitEvent(0, g_evCsr, 0);

    k_edge_accum<<<NEX, 256>>>(e, pairs_v, n_reg_weight, e_reg_sum, e_out);

    dim3 g2((NEX + BM - 1) / BM, HD / BN);
    k_gemm_bf16<false><<<g2, 256>>>(e_out, W2, b2, e_weight, NEX);

    k_vertex_accum<<<NVX, 256>>>(v, pairs_e, e_reg_weight, n_reg_sum, n_weight, v_out);
}

// round 5
// speedup vs baseline: 1.0810x; 1.0810x over previous
#include <cuda_runtime.h>
#include <cuda_bf16.h>

#define NVX 50000
#define NEX 10000
#define HD  256
#define PX  400000

// ---------------- scratch (static device globals; no runtime alloc) ----------------
__device__ float g_ve[(size_t)NVX * HD];   // relu(v @ W1^T + b1) * n_weight
__device__ float g_ev[(size_t)NEX * HD];   // relu(e_out @ W2^T + b2) * e_weight
__device__ __nv_bfloat16 g_vh[(size_t)NVX * HD], g_vl[(size_t)NVX * HD];  // split of v
__device__ __nv_bfloat16 g_eh[(size_t)NEX * HD], g_el[(size_t)NEX * HD];  // split of e_out
__device__ __nv_bfloat16 g_w1h[HD * HD], g_w1l[HD * HD];
__device__ __nv_bfloat16 g_w2h[HD * HD], g_w2l[HD * HD];
__device__ int g_cnt_e[NEX];
__device__ int g_off_e[NEX + 1];
__device__ int g_cur_e[NEX];
__device__ int g_perm_e[PX];
__device__ int g_cnt_v[NVX];
__device__ int g_off_v[NVX + 1];
__device__ int g_cur_v[NVX];
__device__ int g_perm_v[PX];

__device__ __forceinline__ unsigned pack_bf16(float x0, float x1) {
    __nv_bfloat16 h0 = __float2bfloat16(x0);
    __nv_bfloat16 h1 = __float2bfloat16(x1);
    return (unsigned)__bfloat16_as_ushort(h0) | ((unsigned)__bfloat16_as_ushort(h1) << 16);
}

// ---------------- operand split passes ----------------
__global__ void k_split_v(const float* __restrict__ v) {
    size_t i = ((size_t)blockIdx.x * blockDim.x + threadIdx.x) * 4;
    if (i >= (size_t)NVX * HD) return;
    float4 x = *(const float4*)&v[i];
    float h0 = __bfloat162float(__float2bfloat16(x.x));
    float h1 = __bfloat162float(__float2bfloat16(x.y));
    float h2 = __bfloat162float(__float2bfloat16(x.z));
    float h3 = __bfloat162float(__float2bfloat16(x.w));
    uint2 hi = make_uint2(pack_bf16(h0, h1), pack_bf16(h2, h3));
    uint2 lo = make_uint2(pack_bf16(x.x - h0, x.y - h1), pack_bf16(x.z - h2, x.w - h3));
    *(uint2*)&g_vh[i] = hi;
    *(uint2*)&g_vl[i] = lo;
}

__global__ void k_split_w(const float* __restrict__ W1, const float* __restrict__ W2) {
    int t = blockIdx.x * blockDim.x + threadIdx.x;          // 0 .. 2*HD*HD/4-1
    const int per = HD * HD / 4;
    const float* src = (t < per) ? W1 : W2;
    __nv_bfloat16* dh = (t < per) ? g_w1h : g_w2h;
    __nv_bfloat16* dl = (t < per) ? g_w1l : g_w2l;
    size_t i = (size_t)(t < per ? t : t - per) * 4;
    float4 x = *(const float4*)&src[i];
    float h0 = __bfloat162float(__float2bfloat16(x.x));
    float h1 = __bfloat162float(__float2bfloat16(x.y));
    float h2 = __bfloat162float(__float2bfloat16(x.z));
    float h3 = __bfloat162float(__float2bfloat16(x.w));
    *(uint2*)&dh[i] = make_uint2(pack_bf16(h0, h1), pack_bf16(h2, h3));
    *(uint2*)&dl[i] = make_uint2(pack_bf16(x.x - h0, x.y - h1), pack_bf16(x.z - h2, x.w - h3));
}

// ---------------- CSR build (fused edge+vertex) ----------------
__global__ void k_zero_all() {
    int i = blockIdx.x * blockDim.x + threadIdx.x;
    if (i < NEX) g_cnt_e[i] = 0;
    if (i < NVX) g_cnt_v[i] = 0;
}

__global__ void k_hist_all(const int* __restrict__ eidx, const int* __restrict__ vidx) {
    int i = blockIdx.x * blockDim.x + threadIdx.x;
    if (i < PX) {
        atomicAdd(&g_cnt_e[eidx[i]], 1);
        atomicAdd(&g_cnt_v[vidx[i]], 1);
    }
}

__global__ void k_scan_all() {
    const bool EDGE = (blockIdx.x == 0);
    const int n = EDGE ? NEX : NVX;
    const int items = (n + 1023) / 1024;
    const int* cnt = EDGE ? g_cnt_e : g_cnt_v;
    int* off = EDGE ? g_off_e : g_off_v;
    int* cur = EDGE ? g_cur_e : g_cur_v;

    __shared__ int wsum[32];
    int t = threadIdx.x;            // blockDim.x == 1024
    int lane = t & 31, wid = t >> 5;
    int start = t * items;
    int end = min(start + items, n);

    int sum = 0;
    for (int i = start; i < end; i++) sum += cnt[i];

    int v = sum;
#pragma unroll
    for (int s = 1; s < 32; s <<= 1) {
        int y = __shfl_up_sync(0xffffffffu, v, s);
        if (lane >= s) v += y;
    }
    if (lane == 31) wsum[wid] = v;
    __syncthreads();
    if (wid == 0) {
        int w = wsum[lane];
        int vi = w;
#pragma unroll
        for (int s = 1; s < 32; s <<= 1) {
            int y = __shfl_up_sync(0xffffffffu, vi, s);
            if (lane >= s) vi += y;
        }
        wsum[lane] = vi - w;
    }
    __syncthreads();

    int excl = wsum[wid] + (v - sum);
    int run = excl;
    for (int i = start; i < end; i++) {
        off[i] = run;
        cur[i] = run;
        run += cnt[i];
    }
    if (t == 1023) off[n] = run;
}

__global__ void k_fill_all(const int* __restrict__ eidx, const int* __restrict__ vidx) {
    int i = blockIdx.x * blockDim.x + threadIdx.x;
    if (i < PX) {
        int pe = atomicAdd(&g_cur_e[eidx[i]], 1);
        g_perm_e[pe] = i;
        int pv = atomicAdd(&g_cur_v[vidx[i]], 1);
        g_perm_v[pv] = i;
    }
}

// ---------------- split-bf16 tensor-core GEMM, cp.async double-buffered ----------
// C[m,n] = relu(sum_k A[m,k]*B[n,k] + bias[n]) * rowscale[m]
// A,B pre-split to bf16 hi/lo; C = Ah*Bh + Ah*Bl + Al*Bh (fp32 accum).
#define BM 128
#define BN 128
#define BK 32
#define SP 20            // smem row stride in b32 (16 data + 4 pad, 80B = 16B-aligned)
#define SMEM_BYTES (8 * BM * SP * 4)   // 2 buffers x 4 arrays x BM*SP u32 = 81920B

__device__ __forceinline__ void mma_bf16(float* c, const unsigned* a, const unsigned* b) {
    asm volatile(
        "mma.sync.aligned.m16n8k16.row.col.f32.bf16.bf16.f32 "
        "{%0,%1,%2,%3}, {%4,%5,%6,%7}, {%8,%9}, {%0,%1,%2,%3};"
        : "+f"(c[0]), "+f"(c[1]), "+f"(c[2]), "+f"(c[3])
        : "r"(a[0]), "r"(a[1]), "r"(a[2]), "r"(a[3]), "r"(b[0]), "r"(b[1]));
}

__device__ __forceinline__ void cp16(unsigned* dst, const void* src) {
    unsigned s = (unsigned)__cvta_generic_to_shared(dst);
    asm volatile("cp.async.cg.shared.global [%0], [%1], 16;" :: "r"(s), "l"(src));
}

template <bool VE>
__global__ void __launch_bounds__(256, 2)
k_gemm_bf16(const float* __restrict__ bias, const float* __restrict__ rowscale, int M) {
    const __nv_bfloat16* __restrict__ Ah = VE ? g_vh : g_eh;
    const __nv_bfloat16* __restrict__ Al = VE ? g_vl : g_el;
    const __nv_bfloat16* __restrict__ Bh = VE ? g_w1h : g_w2h;
    const __nv_bfloat16* __restrict__ Bl = VE ? g_w1l : g_w2l;
    float* C = VE ? g_ve : g_ev;

    extern __shared__ unsigned smem_u[];
    unsigned* sA_hi = smem_u;                    // [2][BM*SP]
    unsigned* sA_lo = smem_u + 2 * BM * SP;
    unsigned* sB_hi = smem_u + 4 * BM * SP;
    unsigned* sB_lo = smem_u + 6 * BM * SP;

    const int tid = threadIdx.x;
    const int bm = blockIdx.x * BM;
    const int bn = blockIdx.y * BN;
    const int wid = tid >> 5, lane = tid & 31;
    const int gid = lane >> 2, tid4 = lane & 3;
    const int wm = (wid & 1) * 64;
    const int wn = (wid >> 1) * 32;

    // cp.async mapping: thread -> row = tid>>1, segs {sg, sg+1}, sg = (tid&1)*2
    const int crow = tid >> 1;
    const int csg = (tid & 1) * 2;
    const int gmc = min(bm + crow, M - 1);       // clamp (excess rows computed, not stored)
    const size_t aBase = (size_t)gmc * HD + csg * 8;
    const size_t bBase = (size_t)(bn + crow) * HD + csg * 8;
    const int dOff = crow * SP + csg * 4;

    float acc[4][4][4];
#pragma unroll
    for (int mt = 0; mt < 4; mt++)
#pragma unroll
        for (int nt = 0; nt < 4; nt++)
#pragma unroll
            for (int q = 0; q < 4; q++) acc[mt][nt][q] = 0.f;

#define CP_STAGE(KT, BUF)                                                     \
    {                                                                         \
        int bo = (BUF) * BM * SP + dOff;                                      \
        size_t ka = aBase + (KT) * BK;                                        \
        size_t kb = bBase + (KT) * BK;                                        \
        cp16(&sA_hi[bo], Ah + ka);     cp16(&sA_hi[bo + 4], Ah + ka + 8);     \
        cp16(&sA_lo[bo], Al + ka);     cp16(&sA_lo[bo + 4], Al + ka + 8);     \
        cp16(&sB_hi[bo], Bh + kb);     cp16(&sB_hi[bo + 4], Bh + kb + 8);     \
        cp16(&sB_lo[bo], Bl + kb);     cp16(&sB_lo[bo + 4], Bl + kb + 8);     \
    }

#define COMPUTE_TILE(BUF)                                                     \
    {                                                                         \
        const unsigned* pAh = sA_hi + (BUF) * BM * SP;                        \
        const unsigned* pAl = sA_lo + (BUF) * BM * SP;                        \
        const unsigned* pBh = sB_hi + (BUF) * BM * SP;                        \
        const unsigned* pBl = sB_lo + (BUF) * BM * SP;                        \
        _Pragma("unroll")                                                     \
        for (int ks = 0; ks < 2; ks++) {                                      \
            unsigned ah[4][4], al[4][4];                                      \
            _Pragma("unroll")                                                 \
            for (int mt = 0; mt < 4; mt++) {                                  \
                int r = wm + mt * 16 + gid;                                   \
                int c = ks * 8 + tid4;                                        \
                ah[mt][0] = pAh[r * SP + c];                                  \
                ah[mt][1] = pAh[(r + 8) * SP + c];                            \
                ah[mt][2] = pAh[r * SP + c + 4];                              \
                ah[mt][3] = pAh[(r + 8) * SP + c + 4];                        \
                al[mt][0] = pAl[r * SP + c];                                  \
                al[mt][1] = pAl[(r + 8) * SP + c];                            \
                al[mt][2] = pAl[r * SP + c + 4];                              \
                al[mt][3] = pAl[(r + 8) * SP + c + 4];                        \
            }                                                                 \
            _Pragma("unroll")                                                 \
            for (int nt = 0; nt < 4; nt++) {                                  \
                int r = wn + nt * 8 + gid;                                    \
                int c = ks * 8 + tid4;                                        \
                unsigned bh[2], bl[2];                                        \
                bh[0] = pBh[r * SP + c];                                      \
                bh[1] = pBh[r * SP + c + 4];                                  \
                bl[0] = pBl[r * SP + c];                                      \
                bl[1] = pBl[r * SP + c + 4];                                  \
                _Pragma("unroll")                                             \
                for (int mt = 0; mt < 4; mt++) {                              \
                    mma_bf16(acc[mt][nt], ah[mt], bh);                        \
                    mma_bf16(acc[mt][nt], ah[mt], bl);                        \
                    mma_bf16(acc[mt][nt], al[mt], bh);                        \
                }                                                             \
            }                                                                 \
        }                                                                     \
    }

    CP_STAGE(0, 0);
    asm volatile("cp.async.commit_group;");
#pragma unroll
    for (int kt = 0; kt < HD / BK; kt++) {
        if (kt + 1 < HD / BK) CP_STAGE(kt + 1, (kt + 1) & 1);
        asm volatile("cp.async.commit_group;");
        asm volatile("cp.async.wait_group 1;");
        __syncthreads();
        COMPUTE_TILE(kt & 1);
        __syncthreads();
    }

#undef CP_STAGE
#undef COMPUTE_TILE

    // ---- epilogue: bias + relu + rowscale ----
#pragma unroll
    for (int mt = 0; mt < 4; mt++) {
        int rm0 = bm + wm + mt * 16 + gid;
        int rm1 = rm0 + 8;
        float sc0 = (rm0 < M) ? rowscale[rm0] : 0.f;
        float sc1 = (rm1 < M) ? rowscale[rm1] : 0.f;
#pragma unroll
        for (int nt = 0; nt < 4; nt++) {
            int cn = bn + wn + nt * 8 + tid4 * 2;
            float b0f = bias[cn], b1f = bias[cn + 1];
            if (rm0 < M) {
                float2 o;
                o.x = fmaxf(acc[mt][nt][0] + b0f, 0.f) * sc0;
                o.y = fmaxf(acc[mt][nt][1] + b1f, 0.f) * sc0;
                *(float2*)&C[(size_t)rm0 * HD + cn] = o;
            }
            if (rm1 < M) {
                float2 o;
                o.x = fmaxf(acc[mt][nt][2] + b0f, 0.f) * sc1;
                o.y = fmaxf(acc[mt][nt][3] + b1f, 0.f) * sc1;
                *(float2*)&C[(size_t)rm1 * HD + cn] = o;
            }
        }
    }
}

// ---------------- pull-based accumulation ----------------
// e_out[j,h] = (e[j,h] + sum g_ve[pairs_v[p],h]*nrw[p]) / ers[j]; also emits bf16 split.
__global__ void k_edge_accum(const float* __restrict__ e, const int* __restrict__ pairs_v,
                             const float* __restrict__ nrw, const float* __restrict__ ers,
                             float* __restrict__ e_out) {
    __shared__ int srow[256];
    __shared__ float sw[256];
    int j = blockIdx.x;
    int h = threadIdx.x;
    int s = g_off_e[j], t = g_off_e[j + 1];
    float acc = e[(size_t)j * HD + h];
    for (int c = s; c < t; c += 256) {
        int i = c + h;
        if (i < t) {
            int p = g_perm_e[i];
            srow[h] = pairs_v[p];
            sw[h] = nrw[p];
        }
        __syncthreads();
        int m = min(256, t - c);
#pragma unroll 4
        for (int q = 0; q < m; q++)
            acc = fmaf(g_ve[(size_t)srow[q] * HD + h], sw[q], acc);
        __syncthreads();
    }
    float res = acc / ers[j];
    e_out[(size_t)j * HD + h] = res;
    float hi = __bfloat162float(__float2bfloat16(res));
    g_eh[(size_t)j * HD + h] = __float2bfloat16(res);       // same rounding as hi
    g_el[(size_t)j * HD + h] = __float2bfloat16(res - hi);
}

__global__ void k_vertex_accum(const float* __restrict__ v, const int* __restrict__ pairs_e,
                               const float* __restrict__ erw, const float* __restrict__ nrs,
                               const float* __restrict__ nw, float* __restrict__ v_out) {
    __shared__ int srow[256];
    __shared__ float sw[256];
    int i0 = blockIdx.x;
    int h = threadIdx.x;
    int s = g_off_v[i0], t = g_off_v[i0 + 1];
    float acc = v[(size_t)i0 * HD + h] * nw[i0];
    for (int c = s; c < t; c += 256) {
        int i = c + h;
        if (i < t) {
            int p = g_perm_v[i];
            srow[h] = pairs_e[p];
            sw[h] = erw[p];
        }
        __syncthreads();
        int m = min(256, t - c);
#pragma unroll 4
        for (int q = 0; q < m; q++)
            acc = fmaf(g_ev[(size_t)srow[q] * HD + h], sw[q], acc);
        __syncthreads();
    }
    v_out[(size_t)i0 * HD + h] = acc / nrs[i0];
}

// ---------------- launcher: fork/join two-stream graph, launches only ----------------
static cudaStream_t g_s1 = nullptr;
static cudaEvent_t g_evFork = nullptr, g_evCsr = nullptr;

extern "C" void kernel_launch(void* const* d_in, const int* in_sizes, int n_in,
                              void* d_out, int out_size) {
    const float* v            = (const float*)d_in[0];
    const float* e            = (const float*)d_in[1];
    const float* W1           = (const float*)d_in[2];
    const float* b1           = (const float*)d_in[3];
    const float* W2           = (const float*)d_in[4];
    const float* b2           = (const float*)d_in[5];
    const float* n_weight     = (const float*)d_in[6];
    const float* e_weight     = (const float*)d_in[7];
    const float* n_reg_weight = (const float*)d_in[8];
    const float* e_reg_weight = (const float*)d_in[9];
    const float* e_reg_sum    = (const float*)d_in[10];
    const float* n_reg_sum    = (const float*)d_in[11];
    const int*   pairs_v      = (const int*)d_in[12];
    const int*   eidx         = (const int*)d_in[13];
    const int*   pairs_e      = (const int*)d_in[14];
    const int*   vidx         = (const int*)d_in[15];

    float* v_out = (float*)d_out;                              // [NVX, HD]
    float* e_out = (float*)d_out + (size_t)NVX * HD;           // [NEX, HD]

    if (!g_s1) {   // one-time setup on the uncaptured correctness call
        cudaStreamCreateWithFlags(&g_s1, cudaStreamNonBlocking);
        cudaEventCreateWithFlags(&g_evFork, cudaEventDisableTiming);
        cudaEventCreateWithFlags(&g_evCsr, cudaEventDisableTiming);
        cudaFuncSetAttribute(k_gemm_bf16<true>,
                             cudaFuncAttributeMaxDynamicSharedMemorySize, SMEM_BYTES);
        cudaFuncSetAttribute(k_gemm_bf16<false>,
                             cudaFuncAttributeMaxDynamicSharedMemorySize, SMEM_BYTES);
    }

    // main: operand splits (GEMM1 prerequisites)
    k_split_v<<<(NVX * HD / 4 + 255) / 256, 256>>>(v);                       // #1
    k_split_w<<<(2 * HD * HD / 4 + 255) / 256, 256>>>(W1, W2);               // #2

    // fork CSR chain onto s1
    cudaEventRecord(g_evFork, 0);
    cudaStreamWaitEvent(g_s1, g_evFork, 0);
    k_zero_all<<<(NVX + 255) / 256, 256, 0, g_s1>>>();                       // #3

    // GEMM1 (4th submitted launch -> ncu sample window)
    dim3 g1((NVX + BM - 1) / BM, HD / BN);
    k_gemm_bf16<true><<<g1, 256, SMEM_BYTES>>>(b1, n_weight, NVX);           // #4

    k_hist_all<<<(PX + 255) / 256, 256, 0, g_s1>>>(eidx, vidx);              // #5
    k_scan_all<<<2, 1024, 0, g_s1>>>();                                      // #6
    k_fill_all<<<(PX + 255) / 256, 256, 0, g_s1>>>(eidx, vidx);              // #7

    // join CSR into main before the accums
    cudaEventRecord(g_evCsr, g_s1);
    cudaStreamWaitEvent(0, g_evCsr, 0);

    k_edge_accum<<<NEX, 256>>>(e, pairs_v, n_reg_weight, e_reg_sum, e_out);  // #8

    dim3 g2((NEX + BM - 1) / BM, HD / BN);
    k_gemm_bf16<false><<<g2, 256, SMEM_BYTES>>>(b2, e_weight, NEX);          // #9

    k_vertex_accum<<<NVX, 256>>>(v, pairs_e, e_reg_weight, n_reg_sum, n_weight, v_out); // #10
}

// round 6
// speedup vs baseline: 1.3162x; 1.2176x over previous
#include <cuda_runtime.h>
#include <cuda_bf16.h>

#define NVX 50000
#define NEX 10000
#define HD  256
#define PX  400000

// ---------------- scratch (static device globals; no runtime alloc) ----------------
__device__ float g_ve[(size_t)NVX * HD];   // relu(v @ W1^T + b1) * n_weight
__device__ float g_ev[(size_t)NEX * HD];   // relu(e_out @ W2^T + b2) * e_weight
__device__ __nv_bfloat16 g_vh[(size_t)NVX * HD], g_vl[(size_t)NVX * HD];  // split of v
__device__ __nv_bfloat16 g_eh[(size_t)NEX * HD], g_el[(size_t)NEX * HD];  // split of e_out
__device__ __nv_bfloat16 g_w1h[HD * HD], g_w1l[HD * HD];
__device__ __nv_bfloat16 g_w2h[HD * HD], g_w2l[HD * HD];
__device__ int g_cnt_e[NEX];
__device__ int g_off_e[NEX + 1];
__device__ int g_cur_e[NEX];
__device__ int g_perm_e[PX];
__device__ int g_cnt_v[NVX];
__device__ int g_off_v[NVX + 1];
__device__ int g_cur_v[NVX];
__device__ int g_perm_v[PX];

__device__ __forceinline__ unsigned pack_bf16(float x0, float x1) {
    __nv_bfloat16 h0 = __float2bfloat16(x0);
    __nv_bfloat16 h1 = __float2bfloat16(x1);
    return (unsigned)__bfloat16_as_ushort(h0) | ((unsigned)__bfloat16_as_ushort(h1) << 16);
}

// ---------------- operand split passes ----------------
__global__ void k_split_v(const float* __restrict__ v) {
    size_t i = ((size_t)blockIdx.x * blockDim.x + threadIdx.x) * 4;
    if (i >= (size_t)NVX * HD) return;
    float4 x = *(const float4*)&v[i];
    float h0 = __bfloat162float(__float2bfloat16(x.x));
    float h1 = __bfloat162float(__float2bfloat16(x.y));
    float h2 = __bfloat162float(__float2bfloat16(x.z));
    float h3 = __bfloat162float(__float2bfloat16(x.w));
    uint2 hi = make_uint2(pack_bf16(h0, h1), pack_bf16(h2, h3));
    uint2 lo = make_uint2(pack_bf16(x.x - h0, x.y - h1), pack_bf16(x.z - h2, x.w - h3));
    *(uint2*)&g_vh[i] = hi;
    *(uint2*)&g_vl[i] = lo;
}

__global__ void k_split_w(const float* __restrict__ W1, const float* __restrict__ W2) {
    int t = blockIdx.x * blockDim.x + threadIdx.x;          // 0 .. 2*HD*HD/4-1
    const int per = HD * HD / 4;
    const float* src = (t < per) ? W1 : W2;
    __nv_bfloat16* dh = (t < per) ? g_w1h : g_w2h;
    __nv_bfloat16* dl = (t < per) ? g_w1l : g_w2l;
    size_t i = (size_t)(t < per ? t : t - per) * 4;
    float4 x = *(const float4*)&src[i];
    float h0 = __bfloat162float(__float2bfloat16(x.x));
    float h1 = __bfloat162float(__float2bfloat16(x.y));
    float h2 = __bfloat162float(__float2bfloat16(x.z));
    float h3 = __bfloat162float(__float2bfloat16(x.w));
    *(uint2*)&dh[i] = make_uint2(pack_bf16(h0, h1), pack_bf16(h2, h3));
    *(uint2*)&dl[i] = make_uint2(pack_bf16(x.x - h0, x.y - h1), pack_bf16(x.z - h2, x.w - h3));
}

// ---------------- CSR build (fused edge+vertex) ----------------
__global__ void k_zero_all() {
    int i = blockIdx.x * blockDim.x + threadIdx.x;
    if (i < NEX) g_cnt_e[i] = 0;
    if (i < NVX) g_cnt_v[i] = 0;
}

__global__ void k_hist_all(const int* __restrict__ eidx, const int* __restrict__ vidx) {
    int i = blockIdx.x * blockDim.x + threadIdx.x;
    if (i < PX) {
        atomicAdd(&g_cnt_e[eidx[i]], 1);
        atomicAdd(&g_cnt_v[vidx[i]], 1);
    }
}

__global__ void k_scan_all() {
    const bool EDGE = (blockIdx.x == 0);
    const int n = EDGE ? NEX : NVX;
    const int items = (n + 1023) / 1024;
    const int* cnt = EDGE ? g_cnt_e : g_cnt_v;
    int* off = EDGE ? g_off_e : g_off_v;
    int* cur = EDGE ? g_cur_e : g_cur_v;

    __shared__ int wsum[32];
    int t = threadIdx.x;            // blockDim.x == 1024
    int lane = t & 31, wid = t >> 5;
    int start = t * items;
    int end = min(start + items, n);

    int sum = 0;
    for (int i = start; i < end; i++) sum += cnt[i];

    int v = sum;
#pragma unroll
    for (int s = 1; s < 32; s <<= 1) {
        int y = __shfl_up_sync(0xffffffffu, v, s);
        if (lane >= s) v += y;
    }
    if (lane == 31) wsum[wid] = v;
    __syncthreads();
    if (wid == 0) {
        int w = wsum[lane];
        int vi = w;
#pragma unroll
        for (int s = 1; s < 32; s <<= 1) {
            int y = __shfl_up_sync(0xffffffffu, vi, s);
            if (lane >= s) vi += y;
        }
        wsum[lane] = vi - w;
    }
    __syncthreads();

    int excl = wsum[wid] + (v - sum);
    int run = excl;
    for (int i = start; i < end; i++) {
        off[i] = run;
        cur[i] = run;
        run += cnt[i];
    }
    if (t == 1023) off[n] = run;
}

__global__ void k_fill_all(const int* __restrict__ eidx, const int* __restrict__ vidx) {
    int i = blockIdx.x * blockDim.x + threadIdx.x;
    if (i < PX) {
        int pe = atomicAdd(&g_cur_e[eidx[i]], 1);
        g_perm_e[pe] = i;
        int pv = atomicAdd(&g_cur_v[vidx[i]], 1);
        g_perm_v[pv] = i;
    }
}

// ---------------- split-bf16 tensor-core GEMM, cp.async double-buffered ----------
// C[m,n] = relu(sum_k A[m,k]*B[n,k] + bias[n]) * rowscale[m]
// A,B pre-split to bf16 hi/lo; C = Ah*Bh + Ah*Bl + Al*Bh (fp32 accum).
#define BM 128
#define BN 128
#define BK 32
#define SP 20            // smem row stride in b32 (16 data + 4 pad, 80B = 16B-aligned)
#define SMEM_BYTES (8 * BM * SP * 4)   // 2 buffers x 4 arrays x BM*SP u32 = 81920B

__device__ __forceinline__ void mma_bf16(float* c, const unsigned* a, const unsigned* b) {
    asm volatile(
        "mma.sync.aligned.m16n8k16.row.col.f32.bf16.bf16.f32 "
        "{%0,%1,%2,%3}, {%4,%5,%6,%7}, {%8,%9}, {%0,%1,%2,%3};"
        : "+f"(c[0]), "+f"(c[1]), "+f"(c[2]), "+f"(c[3])
        : "r"(a[0]), "r"(a[1]), "r"(a[2]), "r"(a[3]), "r"(b[0]), "r"(b[1]));
}

__device__ __forceinline__ void cp16(unsigned* dst, const void* src) {
    unsigned s = (unsigned)__cvta_generic_to_shared(dst);
    asm volatile("cp.async.cg.shared.global [%0], [%1], 16;" :: "r"(s), "l"(src));
}

template <bool VE>
__global__ void __launch_bounds__(256, 2)
k_gemm_bf16(const float* __restrict__ bias, const float* __restrict__ rowscale, int M) {
    const __nv_bfloat16* __restrict__ Ah = VE ? g_vh : g_eh;
    const __nv_bfloat16* __restrict__ Al = VE ? g_vl : g_el;
    const __nv_bfloat16* __restrict__ Bh = VE ? g_w1h : g_w2h;
    const __nv_bfloat16* __restrict__ Bl = VE ? g_w1l : g_w2l;
    float* C = VE ? g_ve : g_ev;

    extern __shared__ unsigned smem_u[];
    unsigned* sA_hi = smem_u;                    // [2][BM*SP]
    unsigned* sA_lo = smem_u + 2 * BM * SP;
    unsigned* sB_hi = smem_u + 4 * BM * SP;
    unsigned* sB_lo = smem_u + 6 * BM * SP;

    const int tid = threadIdx.x;
    const int bm = blockIdx.x * BM;
    const int bn = blockIdx.y * BN;
    const int wid = tid >> 5, lane = tid & 31;
    const int gid = lane >> 2, tid4 = lane & 3;
    const int wm = (wid & 1) * 64;
    const int wn = (wid >> 1) * 32;

    const int crow = tid >> 1;
    const int csg = (tid & 1) * 2;
    const int gmc = min(bm + crow, M - 1);       // clamp (excess rows computed, not stored)
    const size_t aBase = (size_t)gmc * HD + csg * 8;
    const size_t bBase = (size_t)(bn + crow) * HD + csg * 8;
    const int dOff = crow * SP + csg * 4;

    float acc[4][4][4];
#pragma unroll
    for (int mt = 0; mt < 4; mt++)
#pragma unroll
        for (int nt = 0; nt < 4; nt++)
#pragma unroll
            for (int q = 0; q < 4; q++) acc[mt][nt][q] = 0.f;

#define CP_STAGE(KT, BUF)                                                     \
    {                                                                         \
        int bo = (BUF) * BM * SP + dOff;                                      \
        size_t ka = aBase + (KT) * BK;                                        \
        size_t kb = bBase + (KT) * BK;                                        \
        cp16(&sA_hi[bo], Ah + ka);     cp16(&sA_hi[bo + 4], Ah + ka + 8);     \
        cp16(&sA_lo[bo], Al + ka);     cp16(&sA_lo[bo + 4], Al + ka + 8);     \
        cp16(&sB_hi[bo], Bh + kb);     cp16(&sB_hi[bo + 4], Bh + kb + 8);     \
        cp16(&sB_lo[bo], Bl + kb);     cp16(&sB_lo[bo + 4], Bl + kb + 8);     \
    }

#define COMPUTE_TILE(BUF)                                                     \
    {                                                                         \
        const unsigned* pAh = sA_hi + (BUF) * BM * SP;                        \
        const unsigned* pAl = sA_lo + (BUF) * BM * SP;                        \
        const unsigned* pBh = sB_hi + (BUF) * BM * SP;                        \
        const unsigned* pBl = sB_lo + (BUF) * BM * SP;                        \
        _Pragma("unroll")                                                     \
        for (int ks = 0; ks < 2; ks++) {                                      \
            unsigned ah[4][4], al[4][4];                                      \
            _Pragma("unroll")                                                 \
            for (int mt = 0; mt < 4; mt++) {                                  \
                int r = wm + mt * 16 + gid;                                   \
                int c = ks * 8 + tid4;                                        \
                ah[mt][0] = pAh[r * SP + c];                                  \
                ah[mt][1] = pAh[(r + 8) * SP + c];                            \
                ah[mt][2] = pAh[r * SP + c + 4];                              \
                ah[mt][3] = pAh[(r + 8) * SP + c + 4];                        \
                al[mt][0] = pAl[r * SP + c];                                  \
                al[mt][1] = pAl[(r + 8) * SP + c];                            \
                al[mt][2] = pAl[r * SP + c + 4];                              \
                al[mt][3] = pAl[(r + 8) * SP + c + 4];                        \
            }                                                                 \
            _Pragma("unroll")                                                 \
            for (int nt = 0; nt < 4; nt++) {                                  \
                int r = wn + nt * 8 + gid;                                    \
                int c = ks * 8 + tid4;                                        \
                unsigned bh[2], bl[2];                                        \
                bh[0] = pBh[r * SP + c];                                      \
                bh[1] = pBh[r * SP + c + 4];                                  \
                bl[0] = pBl[r * SP + c];                                      \
                bl[1] = pBl[r * SP + c + 4];                                  \
                _Pragma("unroll")                                             \
                for (int mt = 0; mt < 4; mt++) {                              \
                    mma_bf16(acc[mt][nt], ah[mt], bh);                        \
                    mma_bf16(acc[mt][nt], ah[mt], bl);                        \
                    mma_bf16(acc[mt][nt], al[mt], bh);                        \
                }                                                             \
            }                                                                 \
        }                                                                     \
    }

    CP_STAGE(0, 0);
    asm volatile("cp.async.commit_group;");
#pragma unroll
    for (int kt = 0; kt < HD / BK; kt++) {
        if (kt + 1 < HD / BK) CP_STAGE(kt + 1, (kt + 1) & 1);
        asm volatile("cp.async.commit_group;");
        asm volatile("cp.async.wait_group 1;");
        __syncthreads();
        COMPUTE_TILE(kt & 1);
        __syncthreads();
    }

#undef CP_STAGE
#undef COMPUTE_TILE

    // ---- epilogue: bias + relu + rowscale ----
#pragma unroll
    for (int mt = 0; mt < 4; mt++) {
        int rm0 = bm + wm + mt * 16 + gid;
        int rm1 = rm0 + 8;
        float sc0 = (rm0 < M) ? rowscale[rm0] : 0.f;
        float sc1 = (rm1 < M) ? rowscale[rm1] : 0.f;
#pragma unroll
        for (int nt = 0; nt < 4; nt++) {
            int cn = bn + wn + nt * 8 + tid4 * 2;
            float b0f = bias[cn], b1f = bias[cn + 1];
            if (rm0 < M) {
                float2 o;
                o.x = fmaxf(acc[mt][nt][0] + b0f, 0.f) * sc0;
                o.y = fmaxf(acc[mt][nt][1] + b1f, 0.f) * sc0;
                *(float2*)&C[(size_t)rm0 * HD + cn] = o;
            }
            if (rm1 < M) {
                float2 o;
                o.x = fmaxf(acc[mt][nt][2] + b0f, 0.f) * sc1;
                o.y = fmaxf(acc[mt][nt][3] + b1f, 0.f) * sc1;
                *(float2*)&C[(size_t)rm1 * HD + cn] = o;
            }
        }
    }
}

// ---------------- warp-per-row pull-based accumulation (no smem, no barriers) ----
// One warp owns one output row; lane l owns columns [8l, 8l+8).
// Incidence metadata is read 32 entries at a time (one per lane) and broadcast
// with shfl; each entry costs the warp 2x LDG.128.

// e_out[j,:] = (e[j,:] + sum g_ve[pairs_v[p],:]*nrw[p]) / ers[j]; emits bf16 split.
__global__ void k_edge_accum(const float* __restrict__ e, const int* __restrict__ pairs_v,
                             const float* __restrict__ nrw, const float* __restrict__ ers,
                             float* __restrict__ e_out) {
    int j = (blockIdx.x * blockDim.x + threadIdx.x) >> 5;
    int lane = threadIdx.x & 31;
    if (j >= NEX) return;
    int s = g_off_e[j], t = g_off_e[j + 1];

    const float4* e4 = (const float4*)&e[(size_t)j * HD];
    float4 a0 = e4[lane * 2], a1 = e4[lane * 2 + 1];

    for (int c = s; c < t; c += 32) {
        int i = c + lane;
        int row = 0; float w = 0.f;
        if (i < t) {
            int p = g_perm_e[i];
            row = pairs_v[p];
            w = nrw[p];
        }
        int m = min(32, t - c);
#pragma unroll 4
        for (int q = 0; q < m; q++) {
            int r = __shfl_sync(0xffffffffu, row, q);
            float wq = __shfl_sync(0xffffffffu, w, q);
            const float4* src = (const float4*)&g_ve[(size_t)r * HD];
            float4 x0 = src[lane * 2], x1 = src[lane * 2 + 1];
            a0.x = fmaf(x0.x, wq, a0.x); a0.y = fmaf(x0.y, wq, a0.y);
            a0.z = fmaf(x0.z, wq, a0.z); a0.w = fmaf(x0.w, wq, a0.w);
            a1.x = fmaf(x1.x, wq, a1.x); a1.y = fmaf(x1.y, wq, a1.y);
            a1.z = fmaf(x1.z, wq, a1.z); a1.w = fmaf(x1.w, wq, a1.w);
        }
    }

    float inv = 1.f / ers[j];
    a0.x *= inv; a0.y *= inv; a0.z *= inv; a0.w *= inv;
    a1.x *= inv; a1.y *= inv; a1.z *= inv; a1.w *= inv;

    float4* o4 = (float4*)&e_out[(size_t)j * HD];
    o4[lane * 2] = a0; o4[lane * 2 + 1] = a1;

    // bf16 hi/lo split for GEMM2 input
    float h[8] = {a0.x, a0.y, a0.z, a0.w, a1.x, a1.y, a1.z, a1.w};
    float hr[8];
#pragma unroll
    for (int q = 0; q < 8; q++) hr[q] = __bfloat162float(__float2bfloat16(h[q]));
    uint4 hv = make_uint4(pack_bf16(h[0], h[1]), pack_bf16(h[2], h[3]),
                          pack_bf16(h[4], h[5]), pack_bf16(h[6], h[7]));
    uint4 lv = make_uint4(pack_bf16(h[0] - hr[0], h[1] - hr[1]),
                          pack_bf16(h[2] - hr[2], h[3] - hr[3]),
                          pack_bf16(h[4] - hr[4], h[5] - hr[5]),
                          pack_bf16(h[6] - hr[6], h[7] - hr[7]));
    *(uint4*)&g_eh[(size_t)j * HD + lane * 8] = hv;
    *(uint4*)&g_el[(size_t)j * HD + lane * 8] = lv;
}

// v_out[i,:] = (v[i,:]*nw[i] + sum g_ev[pairs_e[p],:]*erw[p]) / nrs[i]
__global__ void k_vertex_accum(const float* __restrict__ v, const int* __restrict__ pairs_e,
                               const float* __restrict__ erw, const float* __restrict__ nrs,
                               const float* __restrict__ nw, float* __restrict__ v_out) {
    int i0 = (blockIdx.x * blockDim.x + threadIdx.x) >> 5;
    int lane = threadIdx.x & 31;
    if (i0 >= NVX) return;
    int s = g_off_v[i0], t = g_off_v[i0 + 1];

    float nwi = nw[i0];
    const float4* v4 = (const float4*)&v[(size_t)i0 * HD];
    float4 a0 = v4[lane * 2], a1 = v4[lane * 2 + 1];
    a0.x *= nwi; a0.y *= nwi; a0.z *= nwi; a0.w *= nwi;
    a1.x *= nwi; a1.y *= nwi; a1.z *= nwi; a1.w *= nwi;

    for (int c = s; c < t; c += 32) {
        int i = c + lane;
        int row = 0; float w = 0.f;
        if (i < t) {
            int p = g_perm_v[i];
            row = pairs_e[p];
            w = erw[p];
        }
        int m = min(32, t - c);
#pragma unroll 4
        for (int q = 0; q < m; q++) {
            int r = __shfl_sync(0xffffffffu, row, q);
            float wq = __shfl_sync(0xffffffffu, w, q);
            const float4* src = (const float4*)&g_ev[(size_t)r * HD];
            float4 x0 = src[lane * 2], x1 = src[lane * 2 + 1];
            a0.x = fmaf(x0.x, wq, a0.x); a0.y = fmaf(x0.y, wq, a0.y);
            a0.z = fmaf(x0.z, wq, a0.z); a0.w = fmaf(x0.w, wq, a0.w);
            a1.x = fmaf(x1.x, wq, a1.x); a1.y = fmaf(x1.y, wq, a1.y);
            a1.z = fmaf(x1.z, wq, a1.z); a1.w = fmaf(x1.w, wq, a1.w);
        }
    }

    float inv = 1.f / nrs[i0];
    a0.x *= inv; a0.y *= inv; a0.z *= inv; a0.w *= inv;
    a1.x *= inv; a1.y *= inv; a1.z *= inv; a1.w *= inv;

    float4* o4 = (float4*)&v_out[(size_t)i0 * HD];
    o4[lane * 2] = a0; o4[lane * 2 + 1] = a1;
}

// ---------------- launcher: fork/join two-stream graph, launches only ----------------
static cudaStream_t g_s1 = nullptr;
static cudaEvent_t g_evFork = nullptr, g_evCsr = nullptr;

extern "C" void kernel_launch(void* const* d_in, const int* in_sizes, int n_in,
                              void* d_out, int out_size) {
    const float* v            = (const float*)d_in[0];
    const float* e            = (const float*)d_in[1];
    const float* W1           = (const float*)d_in[2];
    const float* b1           = (const float*)d_in[3];
    const float* W2           = (const float*)d_in[4];
    const float* b2           = (const float*)d_in[5];
    const float* n_weight     = (const float*)d_in[6];
    const float* e_weight     = (const float*)d_in[7];
    const float* n_reg_weight = (const float*)d_in[8];
    const float* e_reg_weight = (const float*)d_in[9];
    const float* e_reg_sum    = (const float*)d_in[10];
    const float* n_reg_sum    = (const float*)d_in[11];
    const int*   pairs_v      = (const int*)d_in[12];
    const int*   eidx         = (const int*)d_in[13];
    const int*   pairs_e      = (const int*)d_in[14];
    const int*   vidx         = (const int*)d_in[15];

    float* v_out = (float*)d_out;                              // [NVX, HD]
    float* e_out = (float*)d_out + (size_t)NVX * HD;           // [NEX, HD]

    if (!g_s1) {   // one-time setup on the uncaptured correctness call
        cudaStreamCreateWithFlags(&g_s1, cudaStreamNonBlocking);
        cudaEventCreateWithFlags(&g_evFork, cudaEventDisableTiming);
        cudaEventCreateWithFlags(&g_evCsr, cudaEventDisableTiming);
        cudaFuncSetAttribute(k_gemm_bf16<true>,
                             cudaFuncAttributeMaxDynamicSharedMemorySize, SMEM_BYTES);
        cudaFuncSetAttribute(k_gemm_bf16<false>,
                             cudaFuncAttributeMaxDynamicSharedMemorySize, SMEM_BYTES);
    }

    // main: operand splits (GEMM1 prerequisites)
    k_split_v<<<(NVX * HD / 4 + 255) / 256, 256>>>(v);                       // #1
    k_split_w<<<(2 * HD * HD / 4 + 255) / 256, 256>>>(W1, W2);               // #2

    // fork CSR chain onto s1
    cudaEventRecord(g_evFork, 0);
    cudaStreamWaitEvent(g_s1, g_evFork, 0);
    k_zero_all<<<(NVX + 255) / 256, 256, 0, g_s1>>>();                       // #3

    // GEMM1 (4th submitted launch -> ncu sample window)
    dim3 g1((NVX + BM - 1) / BM, HD / BN);
    k_gemm_bf16<true><<<g1, 256, SMEM_BYTES>>>(b1, n_weight, NVX);           // #4

    k_hist_all<<<(PX + 255) / 256, 256, 0, g_s1>>>(eidx, vidx);              // #5
    k_scan_all<<<2, 1024, 0, g_s1>>>();                                      // #6
    k_fill_all<<<(PX + 255) / 256, 256, 0, g_s1>>>(eidx, vidx);              // #7

    // join CSR into main before the accums
    cudaEventRecord(g_evCsr, g_s1);
    cudaStreamWaitEvent(0, g_evCsr, 0);

    // warp-per-row accums: 8 rows per 256-thread block
    k_edge_accum<<<(NEX + 7) / 8, 256>>>(e, pairs_v, n_reg_weight, e_reg_sum, e_out);   // #8

    dim3 g2((NEX + BM - 1) / BM, HD / BN);
    k_gemm_bf16<false><<<g2, 256, SMEM_BYTES>>>(b2, e_weight, NEX);          // #9

    k_vertex_accum<<<(NVX + 7) / 8, 256>>>(v, pairs_e, e_reg_weight, n_reg_sum, n_weight, v_out); // #10
}